// round 7
// baseline (speedup 1.0000x reference)
#include <cuda_runtime.h>
#include <cuda_fp16.h>
#include <cstdint>

#define B_SZ    8192
#define DK      128
#define EPSV    1e-6f
#define CEPS    (128.0f * 1e-6f * 1e-6f)
#define MARGINF 0.2f

// SMEM tile geometry: 128 rows x 128 halfs, row stride 272 B (256 + 16 pad)
// -> row start bank-word = 68r mod 32 = 4r mod 32: 8 consecutive rows hit
//    distinct 4-word groups covering all 32 banks -> conflict-free ldmatrix.
#define RSTRIDE 272
#define TILE_B  (128 * RSTRIDE)            // 34816
#define SM_A    0                          // A hi tile, then A lo tile
#define OFF_LO  TILE_B
#define SM_B0   (2 * TILE_B)               // 69632
#define OFF_N2  (2 * TILE_B)               // within a B buffer: after hi+lo
#define OFF_TG  (2 * TILE_B + 512)
#define BUFSZ   (2 * TILE_B + 640)         // 70272
#define SM_B1   (SM_B0 + BUFSZ)
#define SMEM_TOTAL (SM_B1 + BUFSZ)         // 210176

// All cp.async sources MUST be 16B aligned -> force alignment on device globals.
__device__ __align__(16) __half  g_e1h[B_SZ * DK];
__device__ __align__(16) __half  g_e1l[B_SZ * DK];
__device__ __align__(16) __half  g_e2h[B_SZ * DK];
__device__ __align__(16) __half  g_e2l[B_SZ * DK];
__device__ __align__(16) float    g_n1[B_SZ];
__device__ __align__(16) float    g_n2[B_SZ];
__device__ __align__(16) unsigned g_posmax[B_SZ];   // float bits; >=0 so uint order == float order
__device__ __align__(16) unsigned g_negmin[B_SZ];
__device__ __align__(16) char     g_tgt[B_SZ];
__device__ int      g_is32;

__device__ __forceinline__ uint32_t smem_u32(const void* p) {
    uint32_t a;
    asm("{ .reg .u64 t; cvta.to.shared.u64 t, %1; cvt.u32.u64 %0, t; }" : "=r"(a) : "l"(p));
    return a;
}

#define CPA16(d, s)  asm volatile("cp.async.cg.shared.global [%0], [%1], 16;" :: "r"(d), "l"(s))
#define CPCOMMIT()   asm volatile("cp.async.commit_group;" ::: "memory")
#define CPWAIT(n)    asm volatile("cp.async.wait_group %0;" :: "n"(n) : "memory")

#define LDSM4(r, addr)                                                          \
    asm volatile("ldmatrix.sync.aligned.m8n8.x4.shared.b16 {%0,%1,%2,%3}, [%4];" \
        : "=r"((r)[0]), "=r"((r)[1]), "=r"((r)[2]), "=r"((r)[3]) : "r"(addr))

#define MMA(C, A, B0v, B1v)                                                     \
    asm volatile(                                                               \
        "mma.sync.aligned.m16n8k16.row.col.f32.f16.f16.f32 "                    \
        "{%0,%1,%2,%3}, {%4,%5,%6,%7}, {%8,%9}, {%0,%1,%2,%3};"                 \
        : "+f"((C)[0]), "+f"((C)[1]), "+f"((C)[2]), "+f"((C)[3])                \
        : "r"((A)[0]), "r"((A)[1]), "r"((A)[2]), "r"((A)[3]),                   \
          "r"(B0v), "r"(B1v))

// ---------------------------------------------------------------------------
// Kernel 0: detect target dtype (int32 vs int64) by OR of odd 32-bit words.
// ---------------------------------------------------------------------------
__global__ void detect_kernel(const unsigned* __restrict__ w) {
    __shared__ unsigned sred[32];
    unsigned acc = 0;
    for (int i = threadIdx.x; i < B_SZ / 2; i += 1024) acc |= w[2 * i + 1];
#pragma unroll
    for (int o = 16; o; o >>= 1) acc |= __shfl_xor_sync(0xFFFFFFFFu, acc, o);
    if ((threadIdx.x & 31) == 0) sred[threadIdx.x >> 5] = acc;
    __syncthreads();
    if (threadIdx.x < 32) {
        acc = sred[threadIdx.x];
#pragma unroll
        for (int o = 16; o; o >>= 1) acc |= __shfl_xor_sync(0xFFFFFFFFu, acc, o);
        if (threadIdx.x == 0) g_is32 = (acc != 0);
    }
}

__device__ __forceinline__ void split4(float4 f, uint32_t hi[2], uint32_t lo[2]) {
    __half hx = __float2half_rn(f.x), hy = __float2half_rn(f.y);
    __half hz = __float2half_rn(f.z), hw = __float2half_rn(f.w);
    __half lx = __float2half_rn(f.x - __half2float(hx));
    __half ly = __float2half_rn(f.y - __half2float(hy));
    __half lz = __float2half_rn(f.z - __half2float(hz));
    __half lw = __float2half_rn(f.w - __half2float(hw));
    __half2 h0 = __halves2half2(hx, hy), h1 = __halves2half2(hz, hw);
    __half2 l0 = __halves2half2(lx, ly), l1 = __halves2half2(lz, lw);
    hi[0] = *(uint32_t*)&h0; hi[1] = *(uint32_t*)&h1;
    lo[0] = *(uint32_t*)&l0; lo[1] = *(uint32_t*)&l1;
}

// ---------------------------------------------------------------------------
// Kernel 1: one-pass split (fp32 -> fp16 hi/lo) + row norms + init + tgt decode.
// One warp per row.
// ---------------------------------------------------------------------------
__global__ void split_kernel(const float* __restrict__ e1, const float* __restrict__ e2,
                             const unsigned* __restrict__ tw) {
    int w   = threadIdx.x >> 5;
    int lid = threadIdx.x & 31;
    int r   = blockIdx.x * 8 + w;

    float4 a = ((const float4*)(e1 + (size_t)r * DK))[lid];
    float4 b = ((const float4*)(e2 + (size_t)r * DK))[lid];

    uint32_t ah[2], al[2], bh[2], bl[2];
    split4(a, ah, al);
    split4(b, bh, bl);
    ((uint2*)(g_e1h + (size_t)r * DK))[lid] = make_uint2(ah[0], ah[1]);
    ((uint2*)(g_e1l + (size_t)r * DK))[lid] = make_uint2(al[0], al[1]);
    ((uint2*)(g_e2h + (size_t)r * DK))[lid] = make_uint2(bh[0], bh[1]);
    ((uint2*)(g_e2l + (size_t)r * DK))[lid] = make_uint2(bl[0], bl[1]);

    float s1 = a.x + a.y + a.z + a.w;
    float q1 = a.x * a.x + a.y * a.y + a.z * a.z + a.w * a.w;
    float s2 = b.x + b.y + b.z + b.w;
    float q2 = b.x * b.x + b.y * b.y + b.z * b.z + b.w * b.w;
#pragma unroll
    for (int o = 16; o; o >>= 1) {
        s1 += __shfl_xor_sync(0xFFFFFFFFu, s1, o);
        q1 += __shfl_xor_sync(0xFFFFFFFFu, q1, o);
        s2 += __shfl_xor_sync(0xFFFFFFFFu, s2, o);
        q2 += __shfl_xor_sync(0xFFFFFFFFu, q2, o);
    }
    if (lid == 0) {
        g_n1[r] = q1 + 2.0f * EPSV * s1;
        g_n2[r] = q2 - 2.0f * EPSV * s2;
        g_posmax[r] = 0u;
        g_negmin[r] = 0x7f800000u;
        g_tgt[r] = (char)(g_is32 ? tw[r] : tw[2 * r]);
    }
}

// ---------------------------------------------------------------------------
// B-chunk loader: 128 columns (rows of e2h/e2l) + per-column n2/tgt metadata.
// ---------------------------------------------------------------------------
__device__ __forceinline__ void load_b_chunk(uint32_t bb, int gcol0, int tid) {
    int row  = tid >> 1;
    int h128 = (tid & 1) * 128;
    const char* sh = (const char*)(g_e2h + (size_t)(gcol0 + row) * DK) + h128;
    const char* sl = (const char*)(g_e2l + (size_t)(gcol0 + row) * DK) + h128;
    uint32_t dh = bb + (uint32_t)row * RSTRIDE + h128;
#pragma unroll
    for (int i = 0; i < 8; i++) {
        CPA16(dh + i * 16, sh + i * 16);
        CPA16(dh + OFF_LO + i * 16, sl + i * 16);
    }
    if (tid < 32) {
        CPA16(bb + OFF_N2 + tid * 16, (const char*)(g_n2 + gcol0) + tid * 16);
    } else if (tid < 40) {
        CPA16(bb + OFF_TG + (tid - 32) * 16, (const char*)(g_tgt + gcol0) + (tid - 32) * 16);
    }
}

// ---------------------------------------------------------------------------
// Kernel 2: row-persistent fp16x3 GEMM + fused masked row max/min.
// Grid (2, 64): by = 128-row block; bx = 4096-column half. 32 chunks of 128.
// 8 warps: wm = w&3 (rows wm*32..+32), wn = w>>2 (cols wn*64..+64).
// A-hi fragments live in registers; A-lo + B streamed via ldmatrix.
// ---------------------------------------------------------------------------
__global__ void __launch_bounds__(256, 1) mma_kernel() {
    extern __shared__ char smem[];
    uint32_t sb = smem_u32(smem);
    int tid  = threadIdx.x;
    int w    = tid >> 5;
    int lane = tid & 31;
    int tq   = lane >> 2;
    int tr   = lane & 3;
    int wm   = w & 3;
    int wn   = w >> 2;
    int r0    = blockIdx.y * 128;
    int cbase = blockIdx.x * 4096;

    // stage A tile (hi + lo)
    {
        int row  = tid >> 1;
        int h128 = (tid & 1) * 128;
        const char* sh = (const char*)(g_e1h + (size_t)(r0 + row) * DK) + h128;
        const char* sl = (const char*)(g_e1l + (size_t)(r0 + row) * DK) + h128;
        uint32_t dh = sb + SM_A + (uint32_t)row * RSTRIDE + h128;
#pragma unroll
        for (int i = 0; i < 8; i++) {
            CPA16(dh + i * 16, sh + i * 16);
            CPA16(dh + OFF_LO + i * 16, sl + i * 16);
        }
    }
    CPCOMMIT();
    load_b_chunk(sb + SM_B0, cbase, tid);        CPCOMMIT();
    load_b_chunk(sb + SM_B1, cbase + 128, tid);  CPCOMMIT();

    CPWAIT(2);            // A staged
    __syncthreads();

    // A-hi fragments -> registers (2 mt x 8 ksteps x 4 regs)
    uint32_t ahr[2][8][4];
    {
        uint32_t abase = sb + SM_A + (uint32_t)(wm * 32 + (lane & 15)) * RSTRIDE
                       + ((lane >> 4) << 4);
#pragma unroll
        for (int mt = 0; mt < 2; mt++)
#pragma unroll
            for (int ks = 0; ks < 8; ks++)
                LDSM4(ahr[mt][ks], abase + mt * 16 * RSTRIDE + ks * 32);
    }

    float n1v[4], maxp[4], minn[4];
#pragma unroll
    for (int s = 0; s < 4; s++) {
        int grow = r0 + wm * 32 + (s >> 1) * 16 + tq + (s & 1) * 8;
        n1v[s]  = g_n1[grow];
        maxp[s] = 0.0f;
        minn[s] = __int_as_float(0x7f800000);
    }

    uint32_t albase = sb + SM_A + OFF_LO + (uint32_t)(wm * 32 + (lane & 15)) * RSTRIDE
                    + ((lane >> 4) << 4);

    for (int j = 0; j < 32; j++) {
        uint32_t bb = sb + ((j & 1) ? SM_B1 : SM_B0);
        if (j < 31) { CPWAIT(1); } else { CPWAIT(0); }
        __syncthreads();

        float c[2][8][4];
#pragma unroll
        for (int mt = 0; mt < 2; mt++)
#pragma unroll
            for (int nt = 0; nt < 8; nt++)
#pragma unroll
                for (int i = 0; i < 4; i++) c[mt][nt][i] = 0.0f;

        uint32_t bbase = bb + (uint32_t)(wn * 64 + (lane & 15)) * RSTRIDE
                       + ((lane >> 4) << 4);
#pragma unroll
        for (int ks = 0; ks < 8; ks++) {
            uint32_t bh[4][4], bl[4][4], alo[2][4];
#pragma unroll
            for (int p = 0; p < 4; p++) LDSM4(bh[p], bbase + p * 16 * RSTRIDE + ks * 32);
#pragma unroll
            for (int p = 0; p < 4; p++) LDSM4(bl[p], bbase + OFF_LO + p * 16 * RSTRIDE + ks * 32);
            LDSM4(alo[0], albase + ks * 32);
            LDSM4(alo[1], albase + 16 * RSTRIDE + ks * 32);
#pragma unroll
            for (int mt = 0; mt < 2; mt++)
#pragma unroll
                for (int p = 0; p < 4; p++) {
                    MMA(c[mt][2 * p],     ahr[mt][ks], bh[p][0], bh[p][2]);
                    MMA(c[mt][2 * p + 1], ahr[mt][ks], bh[p][1], bh[p][3]);
                    MMA(c[mt][2 * p],     ahr[mt][ks], bl[p][0], bl[p][2]);
                    MMA(c[mt][2 * p + 1], ahr[mt][ks], bl[p][1], bl[p][3]);
                    MMA(c[mt][2 * p],     alo[mt],     bh[p][0], bh[p][2]);
                    MMA(c[mt][2 * p + 1], alo[mt],     bh[p][1], bh[p][3]);
                }
        }

        // epilogue: fold chunk into per-row max/min registers
        const float* n2b = (const float*)(smem + ((j & 1) ? SM_B1 : SM_B0) + OFF_N2);
        const char*  tgb = (const char*)(smem + ((j & 1) ? SM_B1 : SM_B0) + OFF_TG);
#pragma unroll
        for (int nt = 0; nt < 8; nt++)
#pragma unroll
            for (int b = 0; b < 2; b++) {
                int jl = wn * 64 + nt * 8 + tr * 2 + b;
                float n2v = n2b[jl];
                char  tv  = tgb[jl];
#pragma unroll
                for (int mt = 0; mt < 2; mt++)
#pragma unroll
                    for (int h = 0; h < 2; h++) {
                        float sq = fmaxf(n1v[mt * 2 + h] + n2v - 2.0f * c[mt][nt][h * 2 + b] + CEPS, 0.0f);
                        if (tv) maxp[mt * 2 + h] = fmaxf(maxp[mt * 2 + h], sq);
                        else    minn[mt * 2 + h] = fminf(minn[mt * 2 + h], sq);
                    }
            }

        __syncthreads();      // all warps done with this buffer
        if (j + 2 < 32) {
            load_b_chunk(bb, cbase + (j + 2) * 128, tid);
            CPCOMMIT();
        }
    }

    // merge quad lanes (xor 1,2 within the 4 lanes sharing each row) + atomics
#pragma unroll
    for (int s = 0; s < 4; s++) {
#pragma unroll
        for (int o = 1; o <= 2; o <<= 1) {
            maxp[s] = fmaxf(maxp[s], __shfl_xor_sync(0xFFFFFFFFu, maxp[s], o));
            minn[s] = fminf(minn[s], __shfl_xor_sync(0xFFFFFFFFu, minn[s], o));
        }
        if (tr == 0) {
            int grow = r0 + wm * 32 + (s >> 1) * 16 + tq + (s & 1) * 8;
            atomicMax(&g_posmax[grow], __float_as_uint(maxp[s]));
            atomicMin(&g_negmin[grow], __float_as_uint(minn[s]));
        }
    }
}

// ---------------------------------------------------------------------------
// Kernel 3: final scalar reduction over anchors (target == 1).
// ---------------------------------------------------------------------------
__global__ void final_kernel(float* __restrict__ out) {
    __shared__ float ss[32];
    __shared__ float sc[32];
    int tid = threadIdx.x;
    float s = 0.0f, c = 0.0f;
#pragma unroll 8
    for (int i = tid; i < B_SZ; i += 1024) {
        if (g_tgt[i]) {
            float pm = __uint_as_float(g_posmax[i]);
            float nm = __uint_as_float(g_negmin[i]);
            float v  = sqrtf(pm) - sqrtf(nm) + MARGINF;
            s += fmaxf(v, 0.0f);
            c += 1.0f;
        }
    }
#pragma unroll
    for (int o = 16; o; o >>= 1) {
        s += __shfl_xor_sync(0xFFFFFFFFu, s, o);
        c += __shfl_xor_sync(0xFFFFFFFFu, c, o);
    }
    if ((tid & 31) == 0) { ss[tid >> 5] = s; sc[tid >> 5] = c; }
    __syncthreads();
    if (tid < 32) {
        s = ss[tid];
        c = sc[tid];
#pragma unroll
        for (int o = 16; o; o >>= 1) {
            s += __shfl_xor_sync(0xFFFFFFFFu, s, o);
            c += __shfl_xor_sync(0xFFFFFFFFu, c, o);
        }
        if (tid == 0) out[0] = s / c;
    }
}

extern "C" void kernel_launch(void* const* d_in, const int* in_sizes, int n_in,
                              void* d_out, int out_size) {
    const float*    e1 = (const float*)d_in[0];
    const float*    e2 = (const float*)d_in[1];
    const unsigned* tw = (const unsigned*)d_in[2];
    float* out = (float*)d_out;

    cudaFuncSetAttribute(mma_kernel, cudaFuncAttributeMaxDynamicSharedMemorySize, SMEM_TOTAL);

    detect_kernel<<<1, 1024>>>(tw);
    split_kernel<<<B_SZ / 8, 256>>>(e1, e2, tw);
    mma_kernel<<<dim3(2, 64), 256, SMEM_TOTAL>>>();
    final_kernel<<<1, 1024>>>(out);
}